// round 15
// baseline (speedup 1.0000x reference)
#include <cuda_runtime.h>
#include <cuda_bf16.h>
#include <math.h>

#define N_NODES 4096
#define N_EDGES 8192
#define D       64
#define D3      67      // D + 3
#define F1      134     // 2*(D+3)
#define F2      201     // 3*(D+3)
#define HS      68      // padded row stride for H / MI / MO (16B-aligned rows)

// ---------------- device scratch (no allocation allowed) --------------------
__device__ int   g_seg_i[N_EDGES];
__device__ int   g_seg_o[N_EDGES];
__device__ __align__(16) float g_H0[N_NODES * HS];   // pad col 67 stays 0 (zero-init)
__device__ __align__(16) float g_H1[N_NODES * HS];
__device__ __align__(16) float g_MI[N_NODES * HS];   // zero-init; re-zeroed by node phase
__device__ __align__(16) float g_MO[N_NODES * HS];

// tree grid-barrier state (padded leaf counters: 128B apart)
__device__ unsigned g_leaf[8 * 32];
__device__ unsigned g_root;
__device__ volatile unsigned g_bar_gen = 0;

// ---------------- fast math helpers ------------------------------------------
__device__ __forceinline__ float tanh_fast(float x) {
    float ax = fabsf(x);
    float e = __expf(-2.f * ax);
    float t = __fdividef(1.f - e, 1.f + e);
    return copysignf(t, x);
}
__device__ __forceinline__ float sigmoid_fast(float x) {
    return 1.f / (1.f + __expf(-x));
}

// ---------------- smem layout (floats) --------------------------------------
#define S_WE1 0                        // 136*64 = 8704 (pad rows 67,135 zero)
#define S_WN1 8704                     // 204*64 = 13056 (pad rows 67,135,203 zero)
#define S_WN2 (8704 + 13056)           // 21760 : 4096
#define S_BE1 (21760 + 4096)           // 25856 : 64
#define S_WE2 (S_BE1 + 64)             // 64
#define S_BN1 (S_WE2 + 64)             // 64
#define S_BN2 (S_BN1 + 64)             // 64
#define S_BUF (S_BN2 + 64)             // 26112 (16B aligned)
#define ET    64                       // edges per tile
#define ESTR  136                      // [bo(68) | bi(68)] per edge
#define NT    32                       // nodes per tile
#define MSTR  204                      // [mi(68) | mo(68) | H(68)] per node
#define S_NH  (S_BUF + NT * MSTR)      // hbuf 32*64 = 2048
#define S_EW  (S_BUF + ET * ESTR)      // 34816 : 64
#define SMEM_FLOATS (S_EW + 64)        // 34880 floats = 139520 B

// ---------------- two-level tree grid barrier --------------------------------
__device__ __forceinline__ void grid_sync(int nblocks) {
    __syncthreads();
    if (threadIdx.x == 0) {
        __threadfence();
        unsigned gen = g_bar_gen;
        int leaf = blockIdx.x & 7;
        unsigned target = (unsigned)(nblocks >> 3) + ((unsigned)leaf < ((unsigned)nblocks & 7u) ? 1u : 0u);
        if (atomicAdd(&g_leaf[leaf * 32], 1u) == target - 1u) {
            atomicExch(&g_leaf[leaf * 32], 0u);
            __threadfence();
            if (atomicAdd(&g_root, 1u) == 7u) {
                atomicExch(&g_root, 0u);
                __threadfence();
                g_bar_gen = gen + 1u;
            }
        }
        while (g_bar_gen == gen) { __nanosleep(32); }
        __threadfence();
    }
    __syncthreads();
}

// ---------------- phase 0: extract indices + input net ----------------------
// Warp-contiguous scan: per LDG.128 the 32 lanes cover 512 contiguous bytes.
__device__ __forceinline__ void ext_scan_one(float4 v, unsigned f4idx,
                                             int* __restrict__ dst) {
    unsigned g = f4idx * 4u;
    int n = g >> 13;
    int e = g & (N_EDGES - 1);
    if (v.x != 0.f) dst[e + 0] = n;
    if (v.y != 0.f) dst[e + 1] = n;
    if (v.z != 0.f) dst[e + 2] = n;
    if (v.w != 0.f) dst[e + 3] = n;
}

__device__ __forceinline__ void ext_scan(const float4* __restrict__ p,
                                         int* __restrict__ dst,
                                         unsigned b0, unsigned stride4) {
    const unsigned total4 = (unsigned)N_NODES * N_EDGES / 4;   // 8,388,608 float4
    for (unsigned b = b0; b < total4; b += stride4) {
        float4 v0 = __ldcs(&p[b + 0]);
        float4 v1 = __ldcs(&p[b + 32]);
        float4 v2 = __ldcs(&p[b + 64]);
        float4 v3 = __ldcs(&p[b + 96]);
        ext_scan_one(v0, b + 0,  dst);
        ext_scan_one(v1, b + 32, dst);
        ext_scan_one(v2, b + 64, dst);
        ext_scan_one(v3, b + 96, dst);
    }
}

__device__ void extract_input_phase(const float* __restrict__ Ri,
                                    const float* __restrict__ Ro,
                                    const float* __restrict__ X,
                                    const float* __restrict__ W_in,
                                    const float* __restrict__ b_in,
                                    int nblocks) {
    unsigned gtid = blockIdx.x * 1024u + threadIdx.x;
    unsigned warp = gtid >> 5;
    unsigned lane = gtid & 31u;
    unsigned b0 = warp * 128u + lane;             // warp owns 128 float4 (2 KB) per iter
    unsigned stride4 = (unsigned)nblocks * 32u * 128u;
    ext_scan((const float4*)Ri, g_seg_i, b0, stride4);
    ext_scan((const float4*)Ro, g_seg_o, b0, stride4);
    // input net: H0 = [tanh(X@W_in + b_in), X], stride HS (pad stays 0)
    for (int i = blockIdx.x * 1024 + threadIdx.x; i < N_NODES * D; i += nblocks * 1024) {
        int n = i >> 6, d = i & 63;
        float x0 = X[n * 3 + 0], x1 = X[n * 3 + 1], x2 = X[n * 3 + 2];
        float h = tanh_fast(x0 * W_in[d] + x1 * W_in[64 + d] + x2 * W_in[128 + d] + b_in[d]);
        g_H0[n * HS + d] = h;
        if (d < 3) g_H0[n * HS + D + d] = X[n * 3 + d];
    }
}

// ---------------- edge phase (+ optional fused scatter) ---------------------
// 2 block-syncs per tile (gather-done, EW-visible); seg read direct from L1.
template<bool SCATTER>
__device__ void edge_phase(const float* __restrict__ H, float* __restrict__ out,
                           const float* __restrict__ be2, float* sm, int nblocks) {
    int t = threadIdx.x;
    for (int tile = blockIdx.x; tile < N_EDGES / ET; tile += nblocks) {
        int e0 = tile * ET;
        // gather B = [bo | bi], 34 float4 per edge (incl. zero pads); seg via L1
        for (int i = t; i < ET * 34; i += 1024) {
            int j = i / 34, c = i - j * 34;
            int half = c / 17, cc = c - half * 17;
            int node = half ? g_seg_i[e0 + j] : g_seg_o[e0 + j];
            float4 v = *((const float4*)(H + node * HS) + cc);
            ((float4*)(sm + S_BUF + j * ESTR))[c] = v;
        }
        __syncthreads();
        if (t < 512) {
            int dg = t & 15;          // 4 output cols
            int ep = t >> 4;          // edge pair 0..31
            int ja = 2 * ep, jb = ja + 1;
            const float4* W4 = (const float4*)(sm + S_WE1);
            const float* Ba = sm + S_BUF + ja * ESTR;
            const float* Bb = sm + S_BUF + jb * ESTR;
            float4 bias = ((const float4*)(sm + S_BE1))[dg];
            float4 A = bias, Bv = bias;
            #pragma unroll 2
            for (int k = 0; k < 136; k++) {    // rows 67,135 are staged zeros
                float4 w = W4[k * 16 + dg];
                float ba = Ba[k], bb = Bb[k];
                A.x += ba * w.x; A.y += ba * w.y; A.z += ba * w.z; A.w += ba * w.w;
                Bv.x += bb * w.x; Bv.y += bb * w.y; Bv.z += bb * w.z; Bv.w += bb * w.w;
            }
            float4 w2 = ((const float4*)(sm + S_WE2))[dg];
            float pa = tanh_fast(A.x) * w2.x + tanh_fast(A.y) * w2.y
                     + tanh_fast(A.z) * w2.z + tanh_fast(A.w) * w2.w;
            float pb = tanh_fast(Bv.x) * w2.x + tanh_fast(Bv.y) * w2.y
                     + tanh_fast(Bv.z) * w2.z + tanh_fast(Bv.w) * w2.w;
            #pragma unroll
            for (int off = 8; off; off >>= 1) {
                pa += __shfl_down_sync(0xffffffffu, pa, off, 16);
                pb += __shfl_down_sync(0xffffffffu, pb, off, 16);
            }
            if (dg == 0) {
                float bb2 = be2[0];
                float ea = sigmoid_fast(pa + bb2);
                float eb = sigmoid_fast(pb + bb2);
                sm[S_EW + ja] = ea; sm[S_EW + jb] = eb;
                if (!SCATTER) { out[e0 + ja] = ea; out[e0 + jb] = eb; }
            }
        }
        __syncthreads();
        if (SCATTER) {
            // 34 float2 atomics per edge per matrix (pad pair adds ew*0)
            for (int i = t; i < ET * 34; i += 1024) {
                int j = i / 34, p = i - j * 34;
                float ew = sm[S_EW + j];
                int k = 2 * p;
                const float* Bj = sm + S_BUF + j * ESTR;
                float2 vI = make_float2(ew * Bj[k],      ew * Bj[k + 1]);
                float2 vO = make_float2(ew * Bj[68 + k], ew * Bj[68 + k + 1]);
                atomicAdd((float2*)&g_MI[g_seg_i[e0 + j] * HS + k], vI);
                atomicAdd((float2*)&g_MO[g_seg_o[e0 + j] * HS + k], vO);
            }
        }
        if (tile + nblocks < N_EDGES / ET) __syncthreads();   // never with 148 blocks
    }
}

// ---------------- node phase (+ fused re-zero of MI/MO) ---------------------
__device__ void node_phase(const float* __restrict__ Hin, float* __restrict__ Hout,
                           const float* __restrict__ X, float* sm, int nblocks) {
    int t = threadIdx.x;
    for (int tile = blockIdx.x; tile < N_NODES / NT; tile += nblocks) {
        int n0 = tile * NT;
        // gather M = [mi | mo | H], 51 float4 per node (incl. pads)
        for (int i = t; i < NT * 51; i += 1024) {
            int j = i / 51, c = i - j * 51;
            int seg = c / 17, cc = c - seg * 17;
            int n = n0 + j;
            float4 v;
            if (seg == 0)      v = *((const float4*)(g_MI + n * HS) + cc);
            else if (seg == 1) v = *((const float4*)(g_MO + n * HS) + cc);
            else               v = *((const float4*)(Hin + n * HS) + cc);
            ((float4*)(sm + S_BUF + j * MSTR))[c] = v;
        }
        __syncthreads();
        float* hbuf = sm + S_NH;
        if (t < 256) {
            int dg = t & 15;
            int np = t >> 4;              // node pair
            int ja = 2 * np, jb = ja + 1;
            const float4* W4 = (const float4*)(sm + S_WN1);
            const float* Ma = sm + S_BUF + ja * MSTR;
            const float* Mb = sm + S_BUF + jb * MSTR;
            float4 bias = ((const float4*)(sm + S_BN1))[dg];
            float4 A = bias, Bv = bias;
            #pragma unroll 2
            for (int k = 0; k < 204; k++) {   // rows 67,135,203 staged zeros
                float4 w = W4[k * 16 + dg];
                float ma = Ma[k], mb = Mb[k];
                A.x += ma * w.x; A.y += ma * w.y; A.z += ma * w.z; A.w += ma * w.w;
                Bv.x += mb * w.x; Bv.y += mb * w.y; Bv.z += mb * w.z; Bv.w += mb * w.w;
            }
            hbuf[ja * 64 + 4 * dg + 0] = tanh_fast(A.x);
            hbuf[ja * 64 + 4 * dg + 1] = tanh_fast(A.y);
            hbuf[ja * 64 + 4 * dg + 2] = tanh_fast(A.z);
            hbuf[ja * 64 + 4 * dg + 3] = tanh_fast(A.w);
            hbuf[jb * 64 + 4 * dg + 0] = tanh_fast(Bv.x);
            hbuf[jb * 64 + 4 * dg + 1] = tanh_fast(Bv.y);
            hbuf[jb * 64 + 4 * dg + 2] = tanh_fast(Bv.z);
            hbuf[jb * 64 + 4 * dg + 3] = tanh_fast(Bv.w);
        }
        __syncthreads();
        if (t < 256) {
            int dg = t & 15;
            int np = t >> 4;
            int ja = 2 * np, jb = ja + 1;
            const float4* W24 = (const float4*)(sm + S_WN2);
            float4 bias2 = ((const float4*)(sm + S_BN2))[dg];
            float4 A2 = bias2, B2 = bias2;
            const float* ha = hbuf + ja * 64;
            const float* hb = hbuf + jb * 64;
            #pragma unroll 4
            for (int j2 = 0; j2 < D; j2++) {
                float4 w = W24[j2 * 16 + dg];
                float va = ha[j2], vb = hb[j2];
                A2.x += va * w.x; A2.y += va * w.y; A2.z += va * w.z; A2.w += va * w.w;
                B2.x += vb * w.x; B2.y += vb * w.y; B2.z += vb * w.z; B2.w += vb * w.w;
            }
            float* oa = Hout + (n0 + ja) * HS + 4 * dg;
            float* ob = Hout + (n0 + jb) * HS + 4 * dg;
            oa[0] = sigmoid_fast(A2.x);
            oa[1] = sigmoid_fast(A2.y);
            oa[2] = sigmoid_fast(A2.z);
            oa[3] = sigmoid_fast(A2.w);
            ob[0] = sigmoid_fast(B2.x);
            ob[1] = sigmoid_fast(B2.y);
            ob[2] = sigmoid_fast(B2.z);
            ob[3] = sigmoid_fast(B2.w);
        }
        // re-zero MI/MO for this tile (vectorized, incl. pad) — gather already
        // consumed them (first sync), so safe without further sync
        {
            float4 z = make_float4(0.f, 0.f, 0.f, 0.f);
            float4* zi = (float4*)(g_MI + n0 * HS);
            float4* zo = (float4*)(g_MO + n0 * HS);
            for (int i = t; i < NT * HS / 4; i += 1024) { zi[i] = z; zo[i] = z; }
        }
        if (t < NT * 3) {
            int j = t / 3, c = t - j * 3;
            Hout[(n0 + j) * HS + D + c] = X[(n0 + j) * 3 + c];
        }
        if (tile + nblocks < N_NODES / NT) __syncthreads();   // never with 148 blocks
    }
}

// ---------------- persistent kernel ------------------------------------------
__global__ void __launch_bounds__(1024, 1)
gnn_persistent(const float* __restrict__ X,
               const float* __restrict__ Ri,  const float* __restrict__ Ro,
               const float* __restrict__ W_in, const float* __restrict__ b_in,
               const float* __restrict__ We1, const float* __restrict__ be1,
               const float* __restrict__ We2, const float* __restrict__ be2,
               const float* __restrict__ Wn1, const float* __restrict__ bn1,
               const float* __restrict__ Wn2, const float* __restrict__ bn2,
               float* __restrict__ out, int nblocks) {
    extern __shared__ float sm[];
    int t = threadIdx.x;
    // stage weights once per block, with zero pad rows matching padded layouts
    for (int i = t; i < F1 * D; i += 1024) {
        int s = i >> 6, d = i & 63;
        int ds = s + (s >= 67 ? 1 : 0);
        sm[S_WE1 + ds * 64 + d] = We1[i];
    }
    for (int i = t; i < F2 * D; i += 1024) {
        int s = i >> 6, d = i & 63;
        int ds = s + s / 67;
        sm[S_WN1 + ds * 64 + d] = Wn1[i];
    }
    for (int i = t; i < D * D; i += 1024) sm[S_WN2 + i] = Wn2[i];
    if (t < 64) {
        sm[S_WE1 + 67 * 64 + t]  = 0.f;
        sm[S_WE1 + 135 * 64 + t] = 0.f;
        sm[S_WN1 + 67 * 64 + t]  = 0.f;
        sm[S_WN1 + 135 * 64 + t] = 0.f;
        sm[S_WN1 + 203 * 64 + t] = 0.f;
        sm[S_BE1 + t] = be1[t];
        sm[S_WE2 + t] = We2[t];
        sm[S_BN1 + t] = bn1[t];
        sm[S_BN2 + t] = bn2[t];
    }

    extract_input_phase(Ri, Ro, X, W_in, b_in, nblocks);
    grid_sync(nblocks);

    float* Hc = g_H0;
    float* Hn = g_H1;
    #pragma unroll 1
    for (int it = 0; it < 3; it++) {
        edge_phase<true>(Hc, nullptr, be2, sm, nblocks);
        grid_sync(nblocks);
        node_phase(Hc, Hn, X, sm, nblocks);
        grid_sync(nblocks);
        float* tmp = Hc; Hc = Hn; Hn = tmp;
    }
    edge_phase<false>(Hc, out, be2, sm, nblocks);
}

// ---------------- launcher ----------------------------------------------------
extern "C" void kernel_launch(void* const* d_in, const int* in_sizes, int n_in,
                              void* d_out, int out_size) {
    const float* X    = (const float*)d_in[0];
    const float* Ri   = (const float*)d_in[1];
    const float* Ro   = (const float*)d_in[2];
    const float* W_in = (const float*)d_in[3];
    const float* b_in = (const float*)d_in[4];
    const float* We1  = (const float*)d_in[5];
    const float* be1  = (const float*)d_in[6];
    const float* We2  = (const float*)d_in[7];
    const float* be2  = (const float*)d_in[8];
    const float* Wn1  = (const float*)d_in[9];
    const float* bn1  = (const float*)d_in[10];
    const float* Wn2  = (const float*)d_in[11];
    const float* bn2  = (const float*)d_in[12];
    float* out = (float*)d_out;

    int dev = 0, nsm = 0;
    cudaGetDevice(&dev);
    cudaDeviceGetAttribute(&nsm, cudaDevAttrMultiProcessorCount, dev);

    cudaFuncSetAttribute(gnn_persistent, cudaFuncAttributeMaxDynamicSharedMemorySize,
                         SMEM_FLOATS * 4);

    gnn_persistent<<<nsm, 1024, SMEM_FLOATS * 4>>>(
        X, Ri, Ro, W_in, b_in, We1, be1, We2, be2, Wn1, bn1, Wn2, bn2, out, nsm);
}

// round 16
// speedup vs baseline: 1.0977x; 1.0977x over previous
#include <cuda_runtime.h>
#include <cuda_bf16.h>
#include <math.h>

#define N_NODES 4096
#define N_EDGES 8192
#define D       64
#define D3      67      // D + 3
#define F1      134     // 2*(D+3)
#define F2      201     // 3*(D+3)
#define HS      68      // padded row stride for H / MI / MO (16B-aligned rows)

// ---------------- device scratch (no allocation allowed) --------------------
__device__ int   g_seg_i[N_EDGES];
__device__ int   g_seg_o[N_EDGES];
__device__ __align__(16) float g_H0[N_NODES * HS];   // pad col 67 stays 0 (zero-init)
__device__ __align__(16) float g_H1[N_NODES * HS];
__device__ __align__(16) float g_MI[N_NODES * HS];   // zero-init; re-zeroed by node phase
__device__ __align__(16) float g_MO[N_NODES * HS];

// grid barrier state
__device__ unsigned g_bar_count = 0;
__device__ volatile unsigned g_bar_gen = 0;

// ---------------- fast math helpers ------------------------------------------
__device__ __forceinline__ float tanh_fast(float x) {
    float ax = fabsf(x);
    float e = __expf(-2.f * ax);
    float t = __fdividef(1.f - e, 1.f + e);
    return copysignf(t, x);
}
__device__ __forceinline__ float sigmoid_fast(float x) {
    return 1.f / (1.f + __expf(-x));
}

// ---------------- smem layout (floats) --------------------------------------
#define S_WE1 0                        // 136*64 = 8704 (pad rows 67,135 zero)
#define S_WN1 8704                     // 204*64 = 13056 (pad rows 67,135,203 zero)
#define S_WN2 (8704 + 13056)           // 21760 : 4096
#define S_BE1 (21760 + 4096)           // 25856 : 64
#define S_WE2 (S_BE1 + 64)             // 64
#define S_BN1 (S_WE2 + 64)             // 64
#define S_BN2 (S_BN1 + 64)             // 64
#define S_BUF (S_BN2 + 64)             // 26112 (16B aligned)
#define ET    56                       // edges per tile -> 147 tiles (~1 per SM)
#define ESTR  136                      // [bo(68) | bi(68)] per edge
#define NT    28                       // nodes per tile -> 147 tiles
#define MSTR  204                      // [mi(68) | mo(68) | H(68)] per node
#define NTILES_E ((N_EDGES + ET - 1) / ET)   // 147
#define NTILES_N ((N_NODES + NT - 1) / NT)   // 147
#define S_NH  (S_BUF + NT * MSTR)      // hbuf 28*64 = 1792 (node phase union)
#define S_EW  (S_BUF + ET * ESTR)      // 26112+7616 = 33728 : 64 (edge phase union)
#define S_SI  (S_EW + 64)              // 64 ints
#define S_SO  (S_SI + 64)              // 64 ints
#define SMEM_FLOATS (S_SO + 64)        // 33920 floats = 135680 B

// ---------------- grid-wide barrier -----------------------------------------
__device__ __forceinline__ void grid_sync(int nblocks) {
    __syncthreads();
    if (threadIdx.x == 0) {
        __threadfence();
        unsigned gen = g_bar_gen;
        if (atomicAdd(&g_bar_count, 1u) == (unsigned)nblocks - 1u) {
            g_bar_count = 0u;
            __threadfence();
            g_bar_gen = gen + 1u;
        } else {
            while (g_bar_gen == gen) { __nanosleep(32); }
        }
        __threadfence();
    }
    __syncthreads();
}

// ---------------- phase 0: extract indices + input net ----------------------
// Warp-contiguous scan: per LDG.128 the 32 lanes cover 512 contiguous bytes.
__device__ __forceinline__ void ext_scan_one(float4 v, unsigned f4idx,
                                             int* __restrict__ dst) {
    unsigned g = f4idx * 4u;
    int n = g >> 13;
    int e = g & (N_EDGES - 1);
    if (v.x != 0.f) dst[e + 0] = n;
    if (v.y != 0.f) dst[e + 1] = n;
    if (v.z != 0.f) dst[e + 2] = n;
    if (v.w != 0.f) dst[e + 3] = n;
}

__device__ __forceinline__ void ext_scan(const float4* __restrict__ p,
                                         int* __restrict__ dst,
                                         unsigned b0, unsigned stride4) {
    const unsigned total4 = (unsigned)N_NODES * N_EDGES / 4;   // 8,388,608 float4
    for (unsigned b = b0; b < total4; b += stride4) {
        float4 v0 = __ldcs(&p[b + 0]);
        float4 v1 = __ldcs(&p[b + 32]);
        float4 v2 = __ldcs(&p[b + 64]);
        float4 v3 = __ldcs(&p[b + 96]);
        ext_scan_one(v0, b + 0,  dst);
        ext_scan_one(v1, b + 32, dst);
        ext_scan_one(v2, b + 64, dst);
        ext_scan_one(v3, b + 96, dst);
    }
}

__device__ void extract_input_phase(const float* __restrict__ Ri,
                                    const float* __restrict__ Ro,
                                    const float* __restrict__ X,
                                    const float* __restrict__ W_in,
                                    const float* __restrict__ b_in,
                                    int nblocks) {
    unsigned gtid = blockIdx.x * 1024u + threadIdx.x;
    unsigned warp = gtid >> 5;
    unsigned lane = gtid & 31u;
    unsigned b0 = warp * 128u + lane;             // warp owns 128 float4 (2 KB) per iter
    unsigned stride4 = (unsigned)nblocks * 32u * 128u;
    ext_scan((const float4*)Ri, g_seg_i, b0, stride4);
    ext_scan((const float4*)Ro, g_seg_o, b0, stride4);
    // input net: H0 = [tanh(X@W_in + b_in), X], stride HS (pad stays 0)
    for (int i = blockIdx.x * 1024 + threadIdx.x; i < N_NODES * D; i += nblocks * 1024) {
        int n = i >> 6, d = i & 63;
        float x0 = X[n * 3 + 0], x1 = X[n * 3 + 1], x2 = X[n * 3 + 2];
        float h = tanh_fast(x0 * W_in[d] + x1 * W_in[64 + d] + x2 * W_in[128 + d] + b_in[d]);
        g_H0[n * HS + d] = h;
        if (d < 3) g_H0[n * HS + D + d] = X[n * 3 + d];
    }
}

// ---------------- edge phase (+ optional fused scatter) ---------------------
template<bool SCATTER>
__device__ void edge_phase(const float* __restrict__ H, float* __restrict__ out,
                           const float* __restrict__ be2, float* sm, int nblocks) {
    int t = threadIdx.x;
    int* sSi = (int*)(sm + S_SI);
    int* sSo = (int*)(sm + S_SO);
    for (int tile = blockIdx.x; tile < NTILES_E; tile += nblocks) {
        int e0 = tile * ET;
        int ne = N_EDGES - e0; if (ne > ET) ne = ET;   // valid edges in this tile
        if (t < ne) { sSi[t] = g_seg_i[e0 + t]; sSo[t] = g_seg_o[e0 + t]; }
        __syncthreads();
        // gather B = [bo | bi], 34 float4 per edge (incl. zero pads)
        for (int i = t; i < ET * 34; i += 1024) {
            int j = i / 34, c = i - j * 34;
            if (j >= ne) continue;
            int half = c / 17, cc = c - half * 17;
            int node = half ? sSi[j] : sSo[j];
            float4 v = *((const float4*)(H + node * HS) + cc);
            ((float4*)(sm + S_BUF + j * ESTR))[c] = v;
        }
        __syncthreads();
        if (t < (ET / 2) * 16) {                 // 448 threads
            int dg = t & 15;          // 4 output cols
            int ep = t >> 4;          // edge pair 0..27
            int ja = 2 * ep, jb = ja + 1;
            const float4* W4 = (const float4*)(sm + S_WE1);
            const float* Ba = sm + S_BUF + ja * ESTR;
            const float* Bb = sm + S_BUF + jb * ESTR;
            float4 bias = ((const float4*)(sm + S_BE1))[dg];
            float4 A = bias, Bv = bias;
            #pragma unroll 2
            for (int k = 0; k < 136; k++) {    // rows 67,135 are staged zeros
                float4 w = W4[k * 16 + dg];
                float ba = Ba[k], bb = Bb[k];
                A.x += ba * w.x; A.y += ba * w.y; A.z += ba * w.z; A.w += ba * w.w;
                Bv.x += bb * w.x; Bv.y += bb * w.y; Bv.z += bb * w.z; Bv.w += bb * w.w;
            }
            float4 w2 = ((const float4*)(sm + S_WE2))[dg];
            float pa = tanh_fast(A.x) * w2.x + tanh_fast(A.y) * w2.y
                     + tanh_fast(A.z) * w2.z + tanh_fast(A.w) * w2.w;
            float pb = tanh_fast(Bv.x) * w2.x + tanh_fast(Bv.y) * w2.y
                     + tanh_fast(Bv.z) * w2.z + tanh_fast(Bv.w) * w2.w;
            #pragma unroll
            for (int off = 8; off; off >>= 1) {
                pa += __shfl_down_sync(0xffffffffu, pa, off, 16);
                pb += __shfl_down_sync(0xffffffffu, pb, off, 16);
            }
            if (dg == 0) {
                float bb2 = be2[0];
                float ea = sigmoid_fast(pa + bb2);
                float eb = sigmoid_fast(pb + bb2);
                if (ja < ne) {
                    sm[S_EW + ja] = ea;
                    if (!SCATTER) out[e0 + ja] = ea;
                }
                if (jb < ne) {
                    sm[S_EW + jb] = eb;
                    if (!SCATTER) out[e0 + jb] = eb;
                }
            }
        }
        __syncthreads();
        if (SCATTER) {
            // 34 float2 atomics per edge per matrix (pad pair adds ew*0)
            for (int i = t; i < ET * 34; i += 1024) {
                int j = i / 34, p = i - j * 34;
                if (j >= ne) continue;
                float ew = sm[S_EW + j];
                int k = 2 * p;
                const float* Bj = sm + S_BUF + j * ESTR;
                float2 vI = make_float2(ew * Bj[k],      ew * Bj[k + 1]);
                float2 vO = make_float2(ew * Bj[68 + k], ew * Bj[68 + k + 1]);
                atomicAdd((float2*)&g_MI[sSi[j] * HS + k], vI);
                atomicAdd((float2*)&g_MO[sSo[j] * HS + k], vO);
            }
            __syncthreads();
        }
    }
}

// ---------------- node phase (+ fused re-zero of MI/MO) ---------------------
__device__ void node_phase(const float* __restrict__ Hin, float* __restrict__ Hout,
                           const float* __restrict__ X, float* sm, int nblocks) {
    int t = threadIdx.x;
    for (int tile = blockIdx.x; tile < NTILES_N; tile += nblocks) {
        int n0 = tile * NT;
        int nn = N_NODES - n0; if (nn > NT) nn = NT;   // valid nodes
        // gather M = [mi | mo | H], 51 float4 per node (incl. pads)
        for (int i = t; i < NT * 51; i += 1024) {
            int j = i / 51, c = i - j * 51;
            if (j >= nn) continue;
            int seg = c / 17, cc = c - seg * 17;
            int n = n0 + j;
            float4 v;
            if (seg == 0)      v = *((const float4*)(g_MI + n * HS) + cc);
            else if (seg == 1) v = *((const float4*)(g_MO + n * HS) + cc);
            else               v = *((const float4*)(Hin + n * HS) + cc);
            ((float4*)(sm + S_BUF + j * MSTR))[c] = v;
        }
        __syncthreads();
        float* hbuf = sm + S_NH;
        if (t < (NT / 2) * 16) {                 // 224 threads
            int dg = t & 15;
            int np = t >> 4;              // node pair
            int ja = 2 * np, jb = ja + 1;
            const float4* W4 = (const float4*)(sm + S_WN1);
            const float* Ma = sm + S_BUF + ja * MSTR;
            const float* Mb = sm + S_BUF + jb * MSTR;
            float4 bias = ((const float4*)(sm + S_BN1))[dg];
            float4 A = bias, Bv = bias;
            #pragma unroll 2
            for (int k = 0; k < 204; k++) {   // rows 67,135,203 staged zeros
                float4 w = W4[k * 16 + dg];
                float ma = Ma[k], mb = Mb[k];
                A.x += ma * w.x; A.y += ma * w.y; A.z += ma * w.z; A.w += ma * w.w;
                Bv.x += mb * w.x; Bv.y += mb * w.y; Bv.z += mb * w.z; Bv.w += mb * w.w;
            }
            hbuf[ja * 64 + 4 * dg + 0] = tanh_fast(A.x);
            hbuf[ja * 64 + 4 * dg + 1] = tanh_fast(A.y);
            hbuf[ja * 64 + 4 * dg + 2] = tanh_fast(A.z);
            hbuf[ja * 64 + 4 * dg + 3] = tanh_fast(A.w);
            hbuf[jb * 64 + 4 * dg + 0] = tanh_fast(Bv.x);
            hbuf[jb * 64 + 4 * dg + 1] = tanh_fast(Bv.y);
            hbuf[jb * 64 + 4 * dg + 2] = tanh_fast(Bv.z);
            hbuf[jb * 64 + 4 * dg + 3] = tanh_fast(Bv.w);
        }
        __syncthreads();
        if (t < (NT / 2) * 16) {
            int dg = t & 15;
            int np = t >> 4;
            int ja = 2 * np, jb = ja + 1;
            const float4* W24 = (const float4*)(sm + S_WN2);
            float4 bias2 = ((const float4*)(sm + S_BN2))[dg];
            float4 A2 = bias2, B2 = bias2;
            const float* ha = hbuf + ja * 64;
            const float* hb = hbuf + jb * 64;
            #pragma unroll 4
            for (int j2 = 0; j2 < D; j2++) {
                float4 w = W24[j2 * 16 + dg];
                float va = ha[j2], vb = hb[j2];
                A2.x += va * w.x; A2.y += va * w.y; A2.z += va * w.z; A2.w += va * w.w;
                B2.x += vb * w.x; B2.y += vb * w.y; B2.z += vb * w.z; B2.w += vb * w.w;
            }
            if (ja < nn) {
                float* oa = Hout + (n0 + ja) * HS + 4 * dg;
                oa[0] = sigmoid_fast(A2.x);
                oa[1] = sigmoid_fast(A2.y);
                oa[2] = sigmoid_fast(A2.z);
                oa[3] = sigmoid_fast(A2.w);
            }
            if (jb < nn) {
                float* ob = Hout + (n0 + jb) * HS + 4 * dg;
                ob[0] = sigmoid_fast(B2.x);
                ob[1] = sigmoid_fast(B2.y);
                ob[2] = sigmoid_fast(B2.z);
                ob[3] = sigmoid_fast(B2.w);
            }
        }
        // re-zero MI/MO for this tile (vectorized, incl. pad)
        {
            float4 z = make_float4(0.f, 0.f, 0.f, 0.f);
            float4* zi = (float4*)(g_MI + n0 * HS);
            float4* zo = (float4*)(g_MO + n0 * HS);
            int lim = nn * (HS / 4);
            for (int i = t; i < lim; i += 1024) { zi[i] = z; zo[i] = z; }
        }
        if (t < NT * 3) {
            int j = t / 3, c = t - j * 3;
            if (j < nn) Hout[(n0 + j) * HS + D + c] = X[(n0 + j) * 3 + c];
        }
        __syncthreads();
    }
}

// ---------------- persistent kernel ------------------------------------------
__global__ void __launch_bounds__(1024, 1)
gnn_persistent(const float* __restrict__ X,
               const float* __restrict__ Ri,  const float* __restrict__ Ro,
               const float* __restrict__ W_in, const float* __restrict__ b_in,
               const float* __restrict__ We1, const float* __restrict__ be1,
               const float* __restrict__ We2, const float* __restrict__ be2,
               const float* __restrict__ Wn1, const float* __restrict__ bn1,
               const float* __restrict__ Wn2, const float* __restrict__ bn2,
               float* __restrict__ out, int nblocks) {
    extern __shared__ float sm[];
    int t = threadIdx.x;
    // stage weights once per block, with zero pad rows matching padded layouts
    for (int i = t; i < F1 * D; i += 1024) {
        int s = i >> 6, d = i & 63;
        int ds = s + (s >= 67 ? 1 : 0);
        sm[S_WE1 + ds * 64 + d] = We1[i];
    }
    for (int i = t; i < F2 * D; i += 1024) {
        int s = i >> 6, d = i & 63;
        int ds = s + s / 67;
        sm[S_WN1 + ds * 64 + d] = Wn1[i];
    }
    for (int i = t; i < D * D; i += 1024) sm[S_WN2 + i] = Wn2[i];
    if (t < 64) {
        sm[S_WE1 + 67 * 64 + t]  = 0.f;
        sm[S_WE1 + 135 * 64 + t] = 0.f;
        sm[S_WN1 + 67 * 64 + t]  = 0.f;
        sm[S_WN1 + 135 * 64 + t] = 0.f;
        sm[S_WN1 + 203 * 64 + t] = 0.f;
        sm[S_BE1 + t] = be1[t];
        sm[S_WE2 + t] = We2[t];
        sm[S_BN1 + t] = bn1[t];
        sm[S_BN2 + t] = bn2[t];
    }

    extract_input_phase(Ri, Ro, X, W_in, b_in, nblocks);
    grid_sync(nblocks);

    float* Hc = g_H0;
    float* Hn = g_H1;
    #pragma unroll 1
    for (int it = 0; it < 3; it++) {
        edge_phase<true>(Hc, nullptr, be2, sm, nblocks);
        grid_sync(nblocks);
        node_phase(Hc, Hn, X, sm, nblocks);
        grid_sync(nblocks);
        float* tmp = Hc; Hc = Hn; Hn = tmp;
    }
    edge_phase<false>(Hc, out, be2, sm, nblocks);
}

// ---------------- launcher ----------------------------------------------------
extern "C" void kernel_launch(void* const* d_in, const int* in_sizes, int n_in,
                              void* d_out, int out_size) {
    const float* X    = (const float*)d_in[0];
    const float* Ri   = (const float*)d_in[1];
    const float* Ro   = (const float*)d_in[2];
    const float* W_in = (const float*)d_in[3];
    const float* b_in = (const float*)d_in[4];
    const float* We1  = (const float*)d_in[5];
    const float* be1  = (const float*)d_in[6];
    const float* We2  = (const float*)d_in[7];
    const float* be2  = (const float*)d_in[8];
    const float* Wn1  = (const float*)d_in[9];
    const float* bn1  = (const float*)d_in[10];
    const float* Wn2  = (const float*)d_in[11];
    const float* bn2  = (const float*)d_in[12];
    float* out = (float*)d_out;

    int dev = 0, nsm = 0;
    cudaGetDevice(&dev);
    cudaDeviceGetAttribute(&nsm, cudaDevAttrMultiProcessorCount, dev);

    cudaFuncSetAttribute(gnn_persistent, cudaFuncAttributeMaxDynamicSharedMemorySize,
                         SMEM_FLOATS * 4);

    gnn_persistent<<<nsm, 1024, SMEM_FLOATS * 4>>>(
        X, Ri, Ro, W_in, b_in, We1, be1, We2, be2, Wn1, bn1, Wn2, bn2, out, nsm);
}